// round 1
// baseline (speedup 1.0000x reference)
#include <cuda_runtime.h>
#include <math.h>

// ---------------------------------------------------------------------------
// OBB label assigner (rotated FCOS-style). N points x G gt oriented boxes.
// Output layout (float32): [labels (N)] [bbox_targets (N*4 row-major)] [angle (N)]
// ---------------------------------------------------------------------------

#define NMAX 22528
#define GMX 32
#define TOPK_K 15
#define BG_LAB 15
#define PI_F   3.14159265358979323846f
#define HPI_F  1.57079632679489661923f

// -------- device scratch (no allocations allowed) --------
__device__ float g_box1[NMAX * 6];    // decoded det box: cx,cy,w,h,cos,sin
__device__ float g_area1[NMAX];       // det w*h
__device__ float g_sm[NMAX * 15];     // softmax probs
__device__ float g_cost[GMX * NMAX];  // column-major per gt
__device__ float g_cent[GMX * NMAX];  // centerness, column-major per gt
__device__ unsigned g_topk[NMAX];     // bit g set => point in top-15 of gt g (cost>0)
__device__ int g_inds[NMAX];
__device__ int g_labels[NMAX];
__device__ int g_counts[GMX];
__device__ int g_anchor[GMX];
__device__ float g_gt[GMX * 8];       // cx,cy,w,h,cos,sin,angle,area

// ---------------------------------------------------------------------------
// Kernel A: per-point decode + softmax, per-gt precompute, scratch init
// ---------------------------------------------------------------------------
__global__ void kA(const float* __restrict__ pts, const float* __restrict__ stride,
                   const float* __restrict__ preds, const float* __restrict__ probs,
                   const float* __restrict__ gtb, int N, int G)
{
    int i = blockIdx.x * blockDim.x + threadIdx.x;
    if (i < G) {
        float cx = gtb[i * 5 + 0], cy = gtb[i * 5 + 1];
        float w = gtb[i * 5 + 2], h = gtb[i * 5 + 3], a = gtb[i * 5 + 4];
        g_gt[i * 8 + 0] = cx; g_gt[i * 8 + 1] = cy;
        g_gt[i * 8 + 2] = w;  g_gt[i * 8 + 3] = h;
        g_gt[i * 8 + 4] = cosf(a); g_gt[i * 8 + 5] = sinf(a);
        g_gt[i * 8 + 6] = a; g_gt[i * 8 + 7] = w * h;
        g_counts[i] = 0;
    }
    if (i >= N) return;
    g_topk[i] = 0u;

    float st = stride[i];
    float d0 = preds[i * 5 + 0] * st, d1 = preds[i * 5 + 1] * st;
    float d2 = preds[i * 5 + 2] * st, d3 = preds[i * 5 + 3] * st;
    float ang = preds[i * 5 + 4];
    float c = cosf(ang), s = sinf(ang);
    float w = d0 + d2, h = d1 + d3;
    float otx = (d2 - d0) * 0.5f, oty = (d3 - d1) * 0.5f;
    float ox = c * otx - s * oty;
    float oy = s * otx + c * oty;
    float cx = pts[i * 2 + 0] + ox, cy = pts[i * 2 + 1] + oy;
    // a = (angle + pi/2) mod pi - pi/2  (jnp.mod: result sign follows divisor)
    float x = ang + HPI_F;
    float r = fmodf(x, PI_F);
    if (r < 0.0f) r += PI_F;
    float a = r - HPI_F;

    g_box1[i * 6 + 0] = cx; g_box1[i * 6 + 1] = cy;
    g_box1[i * 6 + 2] = w;  g_box1[i * 6 + 3] = h;
    g_box1[i * 6 + 4] = cosf(a); g_box1[i * 6 + 5] = sinf(a);
    g_area1[i] = w * h;

    // softmax over 15 classes (max-subtracted like jax.nn.softmax)
    float p[15];
    float m = -1e30f;
#pragma unroll
    for (int k = 0; k < 15; k++) { p[k] = probs[i * 15 + k]; m = fmaxf(m, p[k]); }
    float sum = 0.0f;
#pragma unroll
    for (int k = 0; k < 15; k++) { p[k] = expf(p[k] - m); sum += p[k]; }
#pragma unroll
    for (int k = 0; k < 15; k++) g_sm[i * 15 + k] = p[k] / sum;
}

// ---------------------------------------------------------------------------
// Rotated IoU of one pair, matching the reference polygon construction.
// ---------------------------------------------------------------------------
__device__ __forceinline__ void make_corners(float cx, float cy, float w, float h,
                                             float c, float s, float* X, float* Y)
{
    float w2 = w * 0.5f, h2 = h * 0.5f;
    // dx = {w2, w2, -w2, -w2}, dy = {-h2, h2, h2, -h2}
    X[0] = cx + (w2 * c + h2 * s);  Y[0] = cy + (w2 * s - h2 * c);
    X[1] = cx + (w2 * c - h2 * s);  Y[1] = cy + (w2 * s + h2 * c);
    X[2] = cx + (-w2 * c - h2 * s); Y[2] = cy + (-w2 * s + h2 * c);
    X[3] = cx + (-w2 * c + h2 * s); Y[3] = cy + (-w2 * s - h2 * c);
}

__device__ float riou_pair(float b1cx, float b1cy, float b1w, float b1h,
                           float b1c, float b1s, float a1,
                           const float* __restrict__ bg /* gt: cx,cy,w,h,c,s,ang,area */)
{
    float b2cx = bg[0], b2cy = bg[1], b2w = bg[2], b2h = bg[3];
    float b2c = bg[4], b2s = bg[5], a2 = bg[7];

    // circumradius early reject (exact: disjoint circles => cnt==0 => inter=0 => iou=0)
    {
        float ddx = b1cx - b2cx, ddy = b1cy - b2cy;
        float r1 = 0.5f * sqrtf(b1w * b1w + b1h * b1h);
        float r2 = 0.5f * sqrtf(b2w * b2w + b2h * b2h);
        float rr = r1 + r2 + 0.5f;
        if (ddx * ddx + ddy * ddy > rr * rr) return 0.0f;
    }

    float c1x[4], c1y[4], c2x[4], c2y[4];
    make_corners(b1cx, b1cy, b1w, b1h, b1c, b1s, c1x, c1y);
    make_corners(b2cx, b2cy, b2w, b2h, b2c, b2s, c2x, c2y);

    float X[24], Y[24], A[24];
    int cnt = 0;
    float sx = 0.0f, sy = 0.0f;

    // 16 edge-edge intersections in the reference's (a-major, b-minor) order
#pragma unroll
    for (int a = 0; a < 4; a++) {
        float px = c1x[a], py = c1y[a];
        float d1x = c1x[(a + 1) & 3] - px, d1y = c1y[(a + 1) & 3] - py;
#pragma unroll
        for (int b = 0; b < 4; b++) {
            float qx = c2x[b], qy = c2y[b];
            float d2x = c2x[(b + 1) & 3] - qx, d2y = c2y[(b + 1) & 3] - qy;
            float den = d1x * d2y - d1y * d2x;
            bool dok = fabsf(den) > 1e-10f;
            float safe = dok ? den : 1.0f;
            float qpx = qx - px, qpy = qy - py;
            float t = (qpx * d2y - qpy * d2x) / safe;
            float u = (qpx * d1y - qpy * d1x) / safe;
            if (dok && t >= 0.0f && t <= 1.0f && u >= 0.0f && u <= 1.0f) {
                float ix = px + t * d1x, iy = py + t * d1y;
                X[cnt] = ix; Y[cnt] = iy; cnt++;
                sx += ix; sy += iy;
            }
        }
    }
    // corners of b1 inside b2
#pragma unroll
    for (int a = 0; a < 4; a++) {
        float rx = c1x[a] - b2cx, ry = c1y[a] - b2cy;
        float xx = rx * b2c + ry * b2s;
        float yy = -rx * b2s + ry * b2c;
        if (fabsf(xx) <= b2w * 0.5f + 1e-6f && fabsf(yy) <= b2h * 0.5f + 1e-6f) {
            X[cnt] = c1x[a]; Y[cnt] = c1y[a]; cnt++;
            sx += c1x[a]; sy += c1y[a];
        }
    }
    // corners of b2 inside b1
#pragma unroll
    for (int b = 0; b < 4; b++) {
        float rx = c2x[b] - b1cx, ry = c2y[b] - b1cy;
        float xx = rx * b1c + ry * b1s;
        float yy = -rx * b1s + ry * b1c;
        if (fabsf(xx) <= b1w * 0.5f + 1e-6f && fabsf(yy) <= b1h * 0.5f + 1e-6f) {
            X[cnt] = c2x[b]; Y[cnt] = c2y[b]; cnt++;
            sx += c2x[b]; sy += c2y[b];
        }
    }

    if (cnt == 0) return 0.0f;
    float ctrx = sx / (float)cnt, ctry = sy / (float)cnt;

    for (int j = 0; j < cnt; j++) A[j] = atan2f(Y[j] - ctry, X[j] - ctrx);
    // stable insertion sort ascending by angle (matches stable jnp.argsort)
    for (int j = 1; j < cnt; j++) {
        float aj = A[j], xj = X[j], yj = Y[j];
        int k = j - 1;
        while (k >= 0 && A[k] > aj) {
            A[k + 1] = A[k]; X[k + 1] = X[k]; Y[k + 1] = Y[k]; k--;
        }
        A[k + 1] = aj; X[k + 1] = xj; Y[k + 1] = yj;
    }
    float acc = 0.0f;
    for (int j = 0; j < cnt; j++) {
        int k = (j + 1 < cnt) ? j + 1 : 0;
        float vax = X[j] - ctrx, vay = Y[j] - ctry;
        float vbx = X[k] - ctrx, vby = Y[k] - ctry;
        acc += vax * vby - vay * vbx;
    }
    float inter = 0.5f * fabsf(acc);
    return inter / fmaxf(a1 + a2 - inter, 1e-8f);
}

// ---------------------------------------------------------------------------
// Kernel B: per-pair cost & centerness. IoU only where valid (cost is masked
// by valid anyway, so skipping is exact).
// ---------------------------------------------------------------------------
__global__ void kB(const float* __restrict__ pts, const float* __restrict__ rr,
                   const float* __restrict__ stride, const int* __restrict__ glab,
                   int N, int G)
{
    __shared__ float sg[GMX * 8];
    __shared__ int sl[GMX];
    int t = threadIdx.y * blockDim.x + threadIdx.x;
    if (t < G * 8) sg[t] = g_gt[t];
    if (t < G) sl[t] = glab[t];
    __syncthreads();

    int g = threadIdx.x;
    int i = blockIdx.x * blockDim.y + threadIdx.y;
    if (i >= N || g >= G) return;

    const float* bg = &sg[g * 8];
    float px = pts[i * 2 + 0], py = pts[i * 2 + 1];
    float offx = px - bg[0], offy = py - bg[1];
    float c = bg[4], s = bg[5], w = bg[2], h = bg[3];
    float ox = offx * c + offy * s;
    float oy = -offx * s + offy * c;
    float t0 = w * 0.5f + ox, t1 = h * 0.5f + oy;
    float t2 = w * 0.5f - ox, t3 = h * 0.5f - oy;
    float mn = fminf(fminf(t0, t1), fminf(t2, t3));
    float mx = fmaxf(fmaxf(t0, t1), fmaxf(t2, t3));
    float u = 2.0f * ox / w, v = 2.0f * oy / h;
    float cent = fmaxf(1.0f - sqrtf((u * u + v * v + 1e-8f) * 0.5f), 0.0f);

    float st = stride[i];
    float crad = 1.5f * st;
    bool inside_gt = (mn > 0.0f) && (fabsf(ox) < crad) && (fabsf(oy) < crad);
    bool inside_rr = (mx >= rr[i * 2 + 0]) && (mx <= rr[i * 2 + 1]);
    bool valid = inside_gt && inside_rr;

    float cost = 0.0f;
    if (valid) {
        float b1cx = g_box1[i * 6 + 0], b1cy = g_box1[i * 6 + 1];
        float b1w = g_box1[i * 6 + 2], b1h = g_box1[i * 6 + 3];
        float b1c = g_box1[i * 6 + 4], b1s = g_box1[i * 6 + 5];
        float iou = riou_pair(b1cx, b1cy, b1w, b1h, b1c, b1s, g_area1[i], bg);
        float prob = g_sm[i * 15 + sl[g]];
        cost = 0.2f * cent + 0.2f * iou + 0.6f * prob;
    }
    g_cost[g * NMAX + i] = cost;
    g_cent[g * NMAX + i] = cent;
}

// ---------------------------------------------------------------------------
// Kernel C: per gt — top-15 of cost (first-index tie-break, iterative argmax,
// destructive masking) + centerness argmax (anchor).
// ---------------------------------------------------------------------------
__global__ void kC(int N, int G)
{
    int g = blockIdx.x;
    int tid = threadIdx.x;
    __shared__ float sv[256];
    __shared__ int si[256];

    for (int it = 0; it < TOPK_K; ++it) {
        float bv = -1.0f; int bi = 0x7fffffff;
        for (int i = tid; i < N; i += 256) {
            float vv = g_cost[g * NMAX + i];
            if (vv > bv || (vv == bv && i < bi)) { bv = vv; bi = i; }
        }
        sv[tid] = bv; si[tid] = bi;
        __syncthreads();
        for (int off = 128; off > 0; off >>= 1) {
            if (tid < off) {
                float v2 = sv[tid + off]; int i2 = si[tid + off];
                if (v2 > sv[tid] || (v2 == sv[tid] && i2 < si[tid])) { sv[tid] = v2; si[tid] = i2; }
            }
            __syncthreads();
        }
        float mv = sv[0]; int mi = si[0];
        if (mv <= 0.0f) break;   // uniform: all threads read same sv[0]
        if (tid == 0) {
            atomicOr(&g_topk[mi], 1u << g);
            g_cost[g * NMAX + mi] = -1.0f;
        }
        __syncthreads();
    }
    __syncthreads();

    // anchor: argmax over points of centerness, first-index tie-break
    {
        float bv = -1e30f; int bi = 0x7fffffff;
        for (int i = tid; i < N; i += 256) {
            float vv = g_cent[g * NMAX + i];
            if (vv > bv || (vv == bv && i < bi)) { bv = vv; bi = i; }
        }
        sv[tid] = bv; si[tid] = bi;
        __syncthreads();
        for (int off = 128; off > 0; off >>= 1) {
            if (tid < off) {
                float v2 = sv[tid + off]; int i2 = si[tid + off];
                if (v2 > sv[tid] || (v2 == sv[tid] && i2 < si[tid])) { sv[tid] = v2; si[tid] = i2; }
            }
            __syncthreads();
        }
        if (tid == 0) g_anchor[g] = si[0];
    }
}

// ---------------------------------------------------------------------------
// Kernel D: per point — argmax area over selected gts, label, counts
// ---------------------------------------------------------------------------
__global__ void kD(const int* __restrict__ glab, int N, int G)
{
    int i = blockIdx.x * blockDim.x + threadIdx.x;
    if (i >= N) return;
    unsigned bits = g_topk[i];
    float best = 0.0f; int bgi = 0;
    for (int g = 0; g < G; ++g) {
        if ((bits >> g) & 1u) {
            float area = g_gt[g * 8 + 7];
            if (area > best) { best = area; bgi = g; }  // first-index on tie
        }
    }
    g_inds[i] = bgi;
    g_labels[i] = (best == 0.0f) ? BG_LAB : glab[bgi];
    if (best != 0.0f) atomicAdd(&g_counts[bgi], 1);
}

// ---------------------------------------------------------------------------
// Kernel E: sequential count-0 anchor override (last gt wins on collision)
// ---------------------------------------------------------------------------
__global__ void kE(const int* __restrict__ glab, int G)
{
    if (blockIdx.x == 0 && threadIdx.x == 0) {
        for (int g = 0; g < G; ++g) {
            if (g_counts[g] == 0) {
                int a = g_anchor[g];
                g_inds[a] = g;
                g_labels[a] = glab[g];
            }
        }
    }
}

// ---------------------------------------------------------------------------
// Kernel F: outputs
// ---------------------------------------------------------------------------
__global__ void kF(const float* __restrict__ pts, const float* __restrict__ stride,
                   float* __restrict__ out, int N, int G)
{
    int i = blockIdx.x * blockDim.x + threadIdx.x;
    if (i >= N) return;
    int g = g_inds[i];
    float cx = g_gt[g * 8 + 0], cy = g_gt[g * 8 + 1];
    float w = g_gt[g * 8 + 2], h = g_gt[g * 8 + 3];
    float c = g_gt[g * 8 + 4], s = g_gt[g * 8 + 5];
    float ang = g_gt[g * 8 + 6];
    float offx = pts[i * 2 + 0] - cx, offy = pts[i * 2 + 1] - cy;
    float ox = offx * c + offy * s;
    float oy = -offx * s + offy * c;
    float st = stride[i];

    out[i] = (float)g_labels[i];
    out[N + i * 4 + 0] = (w * 0.5f + ox) / st;
    out[N + i * 4 + 1] = (h * 0.5f + oy) / st;
    out[N + i * 4 + 2] = (w * 0.5f - ox) / st;
    out[N + i * 4 + 3] = (h * 0.5f - oy) / st;
    out[N * 5 + i] = ang;
}

// ---------------------------------------------------------------------------
extern "C" void kernel_launch(void* const* d_in, const int* in_sizes, int n_in,
                              void* d_out, int out_size)
{
    const float* points = (const float*)d_in[0];
    const float* rr     = (const float*)d_in[1];
    const float* stride = (const float*)d_in[2];
    const float* gtb    = (const float*)d_in[3];
    const int*   glab   = (const int*)d_in[4];
    const float* preds  = (const float*)d_in[5];
    const float* probs  = (const float*)d_in[6];
    float* out = (float*)d_out;

    int N = in_sizes[0] / 2;
    int G = in_sizes[3] / 5;
    if (G > GMX) G = GMX;
    if (N > NMAX) N = NMAX;

    kA<<<(N + 255) / 256, 256>>>(points, stride, preds, probs, gtb, N, G);
    dim3 blk(32, 8);
    kB<<<(N + 7) / 8, blk>>>(points, rr, stride, glab, N, G);
    kC<<<G, 256>>>(N, G);
    kD<<<(N + 255) / 256, 256>>>(glab, N, G);
    kE<<<1, 1>>>(glab, G);
    kF<<<(N + 255) / 256, 256>>>(points, stride, out, N, G);
}

// round 3
// speedup vs baseline: 2.2590x; 2.2590x over previous
#include <cuda_runtime.h>
#include <math.h>

#define NMAX 22528
#define GMX 32
#define LCAP 2048
#define TOPK_K 15
#define BG_LAB 15
#define PI_F   3.14159265358979323846f
#define HPI_F  1.57079632679489661923f

// -------- device scratch --------
__device__ float g_box1[NMAX * 6];    // decoded det box: cx,cy,w,h,cos,sin
__device__ float g_area1[NMAX];
__device__ float g_sm[NMAX * 15];     // softmax probs
__device__ float g_gt[GMX * 8];       // cx,cy,w,h,cos,sin,angle,area
__device__ unsigned g_topk[NMAX];     // bit g => selected by gt g
__device__ int g_ovr[NMAX];           // anchor override gt (-1 none)
__device__ int g_cnt[GMX];            // valid-pair list counters
__device__ float g_lv[GMX * LCAP];    // list values (cost)
__device__ int   g_li[GMX * LCAP];    // list point indices
__device__ unsigned long long g_anchorKey[GMX];

// ---------------------------------------------------------------------------
// Kernel A: per-point decode + softmax + scratch init, per-gt precompute
// ---------------------------------------------------------------------------
__global__ void kA(const float* __restrict__ pts, const float* __restrict__ stride,
                   const float* __restrict__ preds, const float* __restrict__ probs,
                   const float* __restrict__ gtb, int N, int G)
{
    int i = blockIdx.x * blockDim.x + threadIdx.x;
    if (i < G) {
        float cx = gtb[i * 5 + 0], cy = gtb[i * 5 + 1];
        float w = gtb[i * 5 + 2], h = gtb[i * 5 + 3], a = gtb[i * 5 + 4];
        g_gt[i * 8 + 0] = cx; g_gt[i * 8 + 1] = cy;
        g_gt[i * 8 + 2] = w;  g_gt[i * 8 + 3] = h;
        g_gt[i * 8 + 4] = cosf(a); g_gt[i * 8 + 5] = sinf(a);
        g_gt[i * 8 + 6] = a; g_gt[i * 8 + 7] = w * h;
        g_cnt[i] = 0;
        g_anchorKey[i] = 0ULL;
    }
    if (i >= N) return;
    g_topk[i] = 0u;
    g_ovr[i] = -1;

    float st = stride[i];
    float d0 = preds[i * 5 + 0] * st, d1 = preds[i * 5 + 1] * st;
    float d2 = preds[i * 5 + 2] * st, d3 = preds[i * 5 + 3] * st;
    float ang = preds[i * 5 + 4];
    float c = cosf(ang), s = sinf(ang);
    float w = d0 + d2, h = d1 + d3;
    float otx = (d2 - d0) * 0.5f, oty = (d3 - d1) * 0.5f;
    float ox = c * otx - s * oty;
    float oy = s * otx + c * oty;
    float cx = pts[i * 2 + 0] + ox, cy = pts[i * 2 + 1] + oy;
    float x = ang + HPI_F;
    float r = fmodf(x, PI_F);
    if (r < 0.0f) r += PI_F;
    float a = r - HPI_F;

    g_box1[i * 6 + 0] = cx; g_box1[i * 6 + 1] = cy;
    g_box1[i * 6 + 2] = w;  g_box1[i * 6 + 3] = h;
    g_box1[i * 6 + 4] = cosf(a); g_box1[i * 6 + 5] = sinf(a);
    g_area1[i] = w * h;

    float p[15];
    float m = -1e30f;
#pragma unroll
    for (int k = 0; k < 15; k++) { p[k] = probs[i * 15 + k]; m = fmaxf(m, p[k]); }
    float sum = 0.0f;
#pragma unroll
    for (int k = 0; k < 15; k++) { p[k] = expf(p[k] - m); sum += p[k]; }
#pragma unroll
    for (int k = 0; k < 15; k++) g_sm[i * 15 + k] = p[k] / sum;
}

// ---------------------------------------------------------------------------
// Rotated IoU (reference-faithful polygon construction)
// ---------------------------------------------------------------------------
__device__ __forceinline__ void make_corners(float cx, float cy, float w, float h,
                                             float c, float s, float* X, float* Y)
{
    float w2 = w * 0.5f, h2 = h * 0.5f;
    X[0] = cx + (w2 * c + h2 * s);  Y[0] = cy + (w2 * s - h2 * c);
    X[1] = cx + (w2 * c - h2 * s);  Y[1] = cy + (w2 * s + h2 * c);
    X[2] = cx + (-w2 * c - h2 * s); Y[2] = cy + (-w2 * s + h2 * c);
    X[3] = cx + (-w2 * c + h2 * s); Y[3] = cy + (-w2 * s - h2 * c);
}

__device__ float riou_pair(float b1cx, float b1cy, float b1w, float b1h,
                           float b1c, float b1s, float a1,
                           float b2cx, float b2cy, float b2w, float b2h,
                           float b2c, float b2s, float a2)
{
    {
        float ddx = b1cx - b2cx, ddy = b1cy - b2cy;
        float r1 = 0.5f * sqrtf(b1w * b1w + b1h * b1h);
        float r2 = 0.5f * sqrtf(b2w * b2w + b2h * b2h);
        float rr = r1 + r2 + 0.5f;
        if (ddx * ddx + ddy * ddy > rr * rr) return 0.0f;
    }

    float c1x[4], c1y[4], c2x[4], c2y[4];
    make_corners(b1cx, b1cy, b1w, b1h, b1c, b1s, c1x, c1y);
    make_corners(b2cx, b2cy, b2w, b2h, b2c, b2s, c2x, c2y);

    float X[24], Y[24], A[24];
    int cnt = 0;
    float sx = 0.0f, sy = 0.0f;

#pragma unroll
    for (int a = 0; a < 4; a++) {
        float px = c1x[a], py = c1y[a];
        float d1x = c1x[(a + 1) & 3] - px, d1y = c1y[(a + 1) & 3] - py;
#pragma unroll
        for (int b = 0; b < 4; b++) {
            float qx = c2x[b], qy = c2y[b];
            float d2x = c2x[(b + 1) & 3] - qx, d2y = c2y[(b + 1) & 3] - qy;
            float den = d1x * d2y - d1y * d2x;
            bool dok = fabsf(den) > 1e-10f;
            float safe = dok ? den : 1.0f;
            float qpx = qx - px, qpy = qy - py;
            float t = (qpx * d2y - qpy * d2x) / safe;
            float u = (qpx * d1y - qpy * d1x) / safe;
            if (dok && t >= 0.0f && t <= 1.0f && u >= 0.0f && u <= 1.0f) {
                float ix = px + t * d1x, iy = py + t * d1y;
                X[cnt] = ix; Y[cnt] = iy; cnt++;
                sx += ix; sy += iy;
            }
        }
    }
#pragma unroll
    for (int a = 0; a < 4; a++) {
        float rx = c1x[a] - b2cx, ry = c1y[a] - b2cy;
        float xx = rx * b2c + ry * b2s;
        float yy = -rx * b2s + ry * b2c;
        if (fabsf(xx) <= b2w * 0.5f + 1e-6f && fabsf(yy) <= b2h * 0.5f + 1e-6f) {
            X[cnt] = c1x[a]; Y[cnt] = c1y[a]; cnt++;
            sx += c1x[a]; sy += c1y[a];
        }
    }
#pragma unroll
    for (int b = 0; b < 4; b++) {
        float rx = c2x[b] - b1cx, ry = c2y[b] - b1cy;
        float xx = rx * b1c + ry * b1s;
        float yy = -rx * b1s + ry * b1c;
        if (fabsf(xx) <= b1w * 0.5f + 1e-6f && fabsf(yy) <= b1h * 0.5f + 1e-6f) {
            X[cnt] = c2x[b]; Y[cnt] = c2y[b]; cnt++;
            sx += c2x[b]; sy += c2y[b];
        }
    }

    if (cnt == 0) return 0.0f;
    float ctrx = sx / (float)cnt, ctry = sy / (float)cnt;

    for (int j = 0; j < cnt; j++) A[j] = atan2f(Y[j] - ctry, X[j] - ctrx);
    for (int j = 1; j < cnt; j++) {
        float aj = A[j], xj = X[j], yj = Y[j];
        int k = j - 1;
        while (k >= 0 && A[k] > aj) {
            A[k + 1] = A[k]; X[k + 1] = X[k]; Y[k + 1] = Y[k]; k--;
        }
        A[k + 1] = aj; X[k + 1] = xj; Y[k + 1] = yj;
    }
    float acc = 0.0f;
    for (int j = 0; j < cnt; j++) {
        int k = (j + 1 < cnt) ? j + 1 : 0;
        float vax = X[j] - ctrx, vay = Y[j] - ctry;
        float vbx = X[k] - ctrx, vby = Y[k] - ctry;
        acc += vax * vby - vay * vbx;
    }
    float inter = 0.5f * fabsf(acc);
    return inter / fmaxf(a1 + a2 - inter, 1e-8f);
}

// ---------------------------------------------------------------------------
// Kernel B: grid = (ceil(N/256), G). One thread per (point, gt) pair.
// Valid pairs compacted into per-gt lists; anchor argmax folded in.
// ---------------------------------------------------------------------------
__global__ void __launch_bounds__(256)
kB(const float* __restrict__ pts, const float* __restrict__ rr,
   const float* __restrict__ stride, const int* __restrict__ glab,
   int N, int G)
{
    int g = blockIdx.y;
    int lane = threadIdx.x & 31;
    int i = blockIdx.x * blockDim.x + threadIdx.x;

    float bcx = __ldg(&g_gt[g * 8 + 0]), bcy = __ldg(&g_gt[g * 8 + 1]);
    float w   = __ldg(&g_gt[g * 8 + 2]), h   = __ldg(&g_gt[g * 8 + 3]);
    float c   = __ldg(&g_gt[g * 8 + 4]), s   = __ldg(&g_gt[g * 8 + 5]);
    float a2  = __ldg(&g_gt[g * 8 + 7]);
    int lab = __ldg(&glab[g]);

    bool inb = (i < N);
    float cost = 0.0f;
    bool valid = false;
    unsigned long long akey = 0ULL;

    if (inb) {
        float px = pts[i * 2 + 0], py = pts[i * 2 + 1];
        float offx = px - bcx, offy = py - bcy;
        float ox = offx * c + offy * s;
        float oy = -offx * s + offy * c;
        float t0 = w * 0.5f + ox, t1 = h * 0.5f + oy;
        float t2 = w * 0.5f - ox, t3 = h * 0.5f - oy;
        float mn = fminf(fminf(t0, t1), fminf(t2, t3));
        float mx = fmaxf(fmaxf(t0, t1), fmaxf(t2, t3));
        float u = 2.0f * ox / w, v = 2.0f * oy / h;
        float cent = fmaxf(1.0f - sqrtf((u * u + v * v + 1e-8f) * 0.5f), 0.0f);
        float st = stride[i];
        float crad = 1.5f * st;
        bool inside_gt = (mn > 0.0f) && (fabsf(ox) < crad) && (fabsf(oy) < crad);
        bool inside_rr = (mx >= rr[i * 2 + 0]) && (mx <= rr[i * 2 + 1]);
        valid = inside_gt && inside_rr;
        if (valid) {
            float iou = riou_pair(g_box1[i * 6 + 0], g_box1[i * 6 + 1],
                                  g_box1[i * 6 + 2], g_box1[i * 6 + 3],
                                  g_box1[i * 6 + 4], g_box1[i * 6 + 5],
                                  g_area1[i],
                                  bcx, bcy, w, h, c, s, a2);
            cost = 0.2f * cent + 0.2f * iou + 0.6f * g_sm[i * 15 + lab];
        }
        akey = ((unsigned long long)__float_as_uint(cent) << 32) | (unsigned)(~(unsigned)i);
    }

    // compact valid pairs (order-independent: kC keys on (cost, idx))
    unsigned bal = __ballot_sync(0xFFFFFFFFu, valid);
    if (bal) {
        int leader = __ffs(bal) - 1;
        int base;
        if (lane == leader) base = atomicAdd(&g_cnt[g], __popc(bal));
        base = __shfl_sync(0xFFFFFFFFu, base, leader);
        if (valid) {
            int pos = base + __popc(bal & ((1u << lane) - 1u));
            if (pos < LCAP) {
                g_lv[g * LCAP + pos] = cost;
                g_li[g * LCAP + pos] = i;
            }
        }
    }

    // warp-reduce anchor key
#pragma unroll
    for (int off = 16; off > 0; off >>= 1) {
        unsigned long long o = __shfl_down_sync(0xFFFFFFFFu, akey, off);
        if (o > akey) akey = o;
    }
    if (lane == 0 && akey != 0ULL) atomicMax(&g_anchorKey[g], akey);
}

// ---------------------------------------------------------------------------
// Kernel C (single block, 1024 thr): warp w = gt w top-15 from compacted list;
// then counts (deduped by area-argmax ownership); then serial override.
// ---------------------------------------------------------------------------
__global__ void __launch_bounds__(1024)
kC(int N, int G)
{
    __shared__ int2 ssel[512];
    __shared__ int sSelCnt;
    __shared__ int sCounts[GMX];
    int tid = threadIdx.x;
    if (tid == 0) sSelCnt = 0;
    if (tid < GMX) sCounts[tid] = 0;
    __syncthreads();

    int g = tid >> 5;
    int lane = tid & 31;
    if (g < G) {
        int n = g_cnt[g];
        if (n > LCAP) n = LCAP;
        unsigned long long used = 0ULL;  // bit k => entry lane + 32k consumed
        for (int it = 0; it < TOPK_K; ++it) {
            float bv = -1.0f; int bi = 0x7fffffff; int bk = -1;
            for (int k = 0; k * 32 + lane < n; ++k) {
                if ((used >> k) & 1ULL) continue;
                int e = k * 32 + lane;
                float v = g_lv[g * LCAP + e];
                int id = g_li[g * LCAP + e];
                if (v > bv || (v == bv && id < bi)) { bv = v; bi = id; bk = k; }
            }
            unsigned long long myKey = (bk >= 0)
                ? (((unsigned long long)__float_as_uint(bv) << 32) | (unsigned)(~(unsigned)bi))
                : 0ULL;
            unsigned long long key = myKey;
#pragma unroll
            for (int off = 16; off > 0; off >>= 1) {
                unsigned long long o = __shfl_down_sync(0xFFFFFFFFu, key, off);
                if (o > key) key = o;
            }
            key = __shfl_sync(0xFFFFFFFFu, key, 0);
            if (key == 0ULL) break;
            if (myKey == key) {  // unique winner (point idx unique per list)
                used |= 1ULL << bk;
                atomicOr(&g_topk[bi], 1u << g);
                int pos = atomicAdd(&sSelCnt, 1);
                ssel[pos] = make_int2(bi, g);
            }
        }
    }
    __syncthreads();

    // counts: each selected point contributes once (owner = lowest set bit)
    int sc = sSelCnt;
    for (int t = tid; t < sc; t += blockDim.x) {
        int i = ssel[t].x, og = ssel[t].y;
        unsigned bits = g_topk[i];
        if ((bits & (0u - bits)) == (1u << og)) {
            float best = 0.0f; int gi = 0;
            for (int q = 0; q < G; ++q) {
                if ((bits >> q) & 1u) {
                    float area = g_gt[q * 8 + 7];
                    if (area > best) { best = area; gi = q; }
                }
            }
            atomicAdd(&sCounts[gi], 1);
        }
    }
    __syncthreads();

    if (tid == 0) {
        for (int q = 0; q < G; ++q) {
            if (sCounts[q] == 0) {
                unsigned long long k = g_anchorKey[q];
                int ai = (int)(~(unsigned)(k & 0xFFFFFFFFULL));
                if (ai >= 0 && ai < N) g_ovr[ai] = q;  // serial: last gt wins
            }
        }
    }
}

// ---------------------------------------------------------------------------
// Kernel F: per-point final assignment + outputs
// ---------------------------------------------------------------------------
__global__ void kF(const float* __restrict__ pts, const float* __restrict__ stride,
                   const int* __restrict__ glab, float* __restrict__ out, int N, int G)
{
    int i = blockIdx.x * blockDim.x + threadIdx.x;
    if (i >= N) return;
    unsigned bits = g_topk[i];
    float best = 0.0f; int gi = 0;
    for (int g = 0; g < G; ++g) {
        if ((bits >> g) & 1u) {
            float area = g_gt[g * 8 + 7];
            if (area > best) { best = area; gi = g; }
        }
    }
    int label = (best == 0.0f) ? BG_LAB : glab[gi];
    int ov = g_ovr[i];
    if (ov >= 0) { gi = ov; label = glab[ov]; }

    float cx = g_gt[gi * 8 + 0], cy = g_gt[gi * 8 + 1];
    float w = g_gt[gi * 8 + 2], h = g_gt[gi * 8 + 3];
    float c = g_gt[gi * 8 + 4], s = g_gt[gi * 8 + 5];
    float ang = g_gt[gi * 8 + 6];
    float offx = pts[i * 2 + 0] - cx, offy = pts[i * 2 + 1] - cy;
    float ox = offx * c + offy * s;
    float oy = -offx * s + offy * c;
    float st = stride[i];

    out[i] = (float)label;
    out[N + i * 4 + 0] = (w * 0.5f + ox) / st;
    out[N + i * 4 + 1] = (h * 0.5f + oy) / st;
    out[N + i * 4 + 2] = (w * 0.5f - ox) / st;
    out[N + i * 4 + 3] = (h * 0.5f - oy) / st;
    out[N * 5 + i] = ang;
}

// ---------------------------------------------------------------------------
extern "C" void kernel_launch(void* const* d_in, const int* in_sizes, int n_in,
                              void* d_out, int out_size)
{
    const float* points = (const float*)d_in[0];
    const float* rr     = (const float*)d_in[1];
    const float* stride = (const float*)d_in[2];
    const float* gtb    = (const float*)d_in[3];
    const int*   glab   = (const int*)d_in[4];
    const float* preds  = (const float*)d_in[5];
    const float* probs  = (const float*)d_in[6];
    float* out = (float*)d_out;

    int N = in_sizes[0] / 2;
    int G = in_sizes[3] / 5;
    if (G > GMX) G = GMX;
    if (N > NMAX) N = NMAX;

    kA<<<(N + 255) / 256, 256>>>(points, stride, preds, probs, gtb, N, G);
    dim3 gridB((N + 255) / 256, G);
    kB<<<gridB, 256>>>(points, rr, stride, glab, N, G);
    kC<<<1, 1024>>>(N, G);
    kF<<<(N + 255) / 256, 256>>>(points, stride, glab, out, N, G);
}